// round 9
// baseline (speedup 1.0000x reference)
#include <cuda_runtime.h>
#include <cstdint>

#define NROWS 8191
#define C2    0.011271055006945017f    /* 2*gamma*log2(e), gamma=1/256 */
#define NGL2  0.0056355275034725085f   /* gamma*log2(e) */

// ---------------- device scratch (no allocation allowed) ----------------
__device__ float g_yt[8192 * 128];   // tf32 yt keys, dims k-permuted within 8
__device__ float g_vt[128 * 8192];   // tf32 V TRANSPOSED [dim][key], keys permuted within 8
__device__ float g_cq[8192];         // -gamma*log2e*||x_i||^2 (rounded x)
__device__ float g_ck[8192];         // -gamma*log2e*||yt_j||^2 ; row 8191 -> -1e30

// stored index of logical k within its 8-block: (k,k+4) become adjacent
__device__ __host__ __forceinline__ int sperm(int k) { return ((k & 3) << 1) | (k >> 2); }

// ---------------- helpers ----------------
__device__ __forceinline__ float tf32r(float x) {
    uint32_t u; asm("cvt.rna.tf32.f32 %0, %1;" : "=r"(u) : "f"(x));
    return __uint_as_float(u);
}
__device__ __forceinline__ float ex2f(float x) {
    float r; asm("ex2.approx.f32 %0, %1;" : "=f"(r) : "f"(x)); return r;
}
__device__ __forceinline__ uint32_t smaddr(const void* p) {
    uint32_t a;
    asm("{ .reg .u64 t; cvta.to.shared.u64 t, %1; cvt.u32.u64 %0, t; }" : "=r"(a) : "l"(p));
    return a;
}
#define CP16(dst, src) \
    asm volatile("cp.async.cg.shared.global [%0], [%1], 16;" \
                 :: "r"(dst), "l"((size_t)__cvta_generic_to_global(src)) : "memory")
#define CP_COMMIT() asm volatile("cp.async.commit_group;" ::: "memory")
#define CP_WAIT1()  asm volatile("cp.async.wait_group 1;" ::: "memory")
#define CP_WAIT0()  asm volatile("cp.async.wait_group 0;" ::: "memory")

__device__ __forceinline__ void mma8(float* c, uint32_t a0, uint32_t a1, uint32_t a2,
                                     uint32_t a3, uint32_t b0, uint32_t b1) {
    asm volatile("mma.sync.aligned.m16n8k8.row.col.f32.tf32.tf32.f32 "
                 "{%0,%1,%2,%3}, {%4,%5,%6,%7}, {%8,%9}, {%0,%1,%2,%3};"
                 : "+f"(c[0]), "+f"(c[1]), "+f"(c[2]), "+f"(c[3])
                 : "r"(a0), "r"(a1), "r"(a2), "r"(a3), "r"(b0), "r"(b1));
}

// ---------------- kernel 1: yt = y @ R^T + t (tf32, dims permuted) ---------
__global__ __launch_bounds__(256) void yt_kernel(const float* __restrict__ y,
                                                 const float* __restrict__ R,
                                                 const float* __restrict__ t)
{
    extern __shared__ char smem[];
    float* yT = (float*)smem;                 // [k][row] stride 68
    float* RT = (float*)(smem + 34816);       // [k][c]   stride 132
    const int tid = threadIdx.x;
    const int r0  = blockIdx.x * 64;

    #pragma unroll
    for (int s = 0; s < 32; s++) {
        int e = tid + s * 256, row = e >> 7, k = e & 127, gr = r0 + row;
        yT[k * 68 + row] = (gr < NROWS) ? y[gr * 128 + k] : 0.0f;
    }
    #pragma unroll
    for (int s = 0; s < 64; s++) {
        int e = tid + s * 256, c = e >> 7, k = e & 127;
        RT[k * 132 + c] = R[e];
    }
    __syncthreads();

    const int tr = tid >> 4, tc = tid & 15;
    float acc[4][8];
    #pragma unroll
    for (int i = 0; i < 4; i++)
        #pragma unroll
        for (int j = 0; j < 8; j++) acc[i][j] = 0.0f;

    const float4* yT4 = (const float4*)yT;
    const float4* RT4 = (const float4*)RT;
    #pragma unroll 8
    for (int k = 0; k < 128; k++) {
        float4 a  = yT4[k * 17 + tr];
        float4 b0 = RT4[k * 33 + tc * 2];
        float4 b1 = RT4[k * 33 + tc * 2 + 1];
        float av[4] = {a.x, a.y, a.z, a.w};
        float bv[8] = {b0.x, b0.y, b0.z, b0.w, b1.x, b1.y, b1.z, b1.w};
        #pragma unroll
        for (int i = 0; i < 4; i++)
            #pragma unroll
            for (int j = 0; j < 8; j++) acc[i][j] += av[i] * bv[j];
    }
    float tv[8];
    #pragma unroll
    for (int j = 0; j < 8; j++) tv[j] = t[tc * 8 + j];
    #pragma unroll
    for (int i = 0; i < 4; i++) {
        int row = r0 + tr * 4 + i;
        #pragma unroll
        for (int j = 0; j < 8; j++)
            g_yt[row * 128 + tc * 8 + sperm(j)] = tf32r(acc[i][j] + tv[j]);
    }
}

// ---------------- kernel 2: scaled norms ----------------
__global__ __launch_bounds__(128) void norm_kernel(const float* __restrict__ X)
{
    const int row = blockIdx.x, which = blockIdx.y;
    float v = which ? g_yt[row * 128 + threadIdx.x]      // permuted order: sum invariant
                    : tf32r(X[row * 128 + threadIdx.x]);
    float s = v * v;
    #pragma unroll
    for (int o = 16; o; o >>= 1) s += __shfl_down_sync(0xFFFFFFFFu, s, o);
    __shared__ float red[4];
    if ((threadIdx.x & 31) == 0) red[threadIdx.x >> 5] = s;
    __syncthreads();
    if (threadIdx.x == 0) {
        float tot = -(red[0] + red[1] + red[2] + red[3]) * NGL2;
        if (which) g_ck[row] = (row < NROWS) ? tot : -1e30f;
        else       g_cq[row] = tot;
    }
}

// ---------------- kernel 3: V transpose [dim][key], keys permuted ----------
__global__ __launch_bounds__(256) void vt_kernel(const float* __restrict__ X)
{
    __shared__ float ts[64 * 133];
    const int tid = threadIdx.x;
    const int j0 = blockIdx.x * 64;

    #pragma unroll
    for (int i = 0; i < 8; i++) {
        int f = tid + i * 256;               // 0..2047
        int r = f >> 5, c4 = f & 31;
        int src = j0 + r + 1; if (src > 8191) src = 8191;  // clamp; weight is 0
        float4 v = ((const float4*)X)[(size_t)src * 32 + c4];
        float* d = &ts[r * 133 + c4 * 4];
        d[0] = v.x; d[1] = v.y; d[2] = v.z; d[3] = v.w;
    }
    __syncthreads();

    const int w = tid >> 5, l = tid & 31;
    #pragma unroll
    for (int db = 0; db < 16; db++) {
        int d = db * 8 + w;
        #pragma unroll
        for (int it = 0; it < 2; it++) {
            int r = it * 32 + l;
            int jst = (r & ~7) | sperm(r & 7);
            g_vt[(size_t)d * 8192 + j0 + jst] = tf32r(ts[r * 133 + d]);
        }
    }
}

// ---------------- kernel 4: flash RBF attention, tf32 mma + v2 loads -------
// grid 128, 512 threads (16 warps): wm=w&3 -> 16-row m-strip, g=w>>2 -> 16-key group.
// smem (floats): Qs[64][132]@0  Ks[2][64][132]@8448  Vs[2][128][68]@25344
//                Ps[64][76]@42752  ck[2][64]@47616   total 47744 f = 190976 B
#define SQ 132
#define SVD 68
#define SP 76
#define QSO 0
#define KSO(b) (8448 + (b) * 8448)
#define VSO(b) (25344 + (b) * 8704)
#define PSO 42752
#define CKO(b) (47616 + (b) * 64)
#define SMEM_BYTES (47744 * 4)

__global__ __launch_bounds__(512, 1) void attn_kernel(const float* __restrict__ X,
                                                      float* __restrict__ out)
{
    extern __shared__ float sm[];
    const int tid = threadIdx.x;
    const int w = tid >> 5, l = tid & 31;
    const int gid = l >> 2, tig = l & 3;
    const int wm = w & 3, g = w >> 2;
    const int m0 = wm * 16;
    const int kb0 = g * 16;
    const int r0 = blockIdx.x * 64;

    // ---- stage Q (tf32, dims permuted) into Qs ----
    {
        const float4* X4 = (const float4*)X;
        #pragma unroll
        for (int i = 0; i < 4; i++) {
            int f = tid + i * 512, r = f >> 5, c4 = f & 31;
            float4 q = X4[(size_t)(r0 + r) * 32 + c4];
            int base = r * SQ + (c4 >> 1) * 8 + (c4 & 1);   // stored col = .. + 2i
            sm[QSO + base + 0] = tf32r(q.x);
            sm[QSO + base + 2] = tf32r(q.y);
            sm[QSO + base + 4] = tf32r(q.z);
            sm[QSO + base + 6] = tf32r(q.w);
        }
    }
    const float cq0 = g_cq[r0 + m0 + gid];
    const float cq1 = g_cq[r0 + m0 + gid + 8];

    // ---- prime tile 0 into buffer 0 ----
    #pragma unroll
    for (int i = 0; i < 4; i++) {
        int f = tid + i * 512, r = f >> 5, c4 = f & 31;
        CP16(smaddr(&sm[KSO(0) + r * SQ + c4 * 4]), g_yt + r * 128 + c4 * 4);
    }
    #pragma unroll
    for (int i = 0; i < 4; i++) {
        int f = tid + i * 512, r = f >> 4, c = f & 15;      // r: dim 0..127
        CP16(smaddr(&sm[VSO(0) + r * SVD + c * 4]), g_vt + (size_t)r * 8192 + c * 4);
    }
    if (tid < 16) CP16(smaddr(&sm[CKO(0) + tid * 4]), g_ck + tid * 4);
    CP_COMMIT();

    float oa[16][4];
    #pragma unroll
    for (int i = 0; i < 16; i++)
        #pragma unroll
        for (int j = 0; j < 4; j++) oa[i][j] = 0.0f;
    float den0 = 0.0f, den1 = 0.0f;

    #pragma unroll 1
    for (int t = 0; t < 128; t++) {
        const int b = t & 1;

        if (t + 1 < 128) {
            const int nb = b ^ 1;
            const int j0 = (t + 1) * 64;
            #pragma unroll
            for (int i = 0; i < 4; i++) {
                int f = tid + i * 512, r = f >> 5, c4 = f & 31;
                CP16(smaddr(&sm[KSO(nb) + r * SQ + c4 * 4]),
                     g_yt + (size_t)(j0 + r) * 128 + c4 * 4);
            }
            #pragma unroll
            for (int i = 0; i < 4; i++) {
                int f = tid + i * 512, r = f >> 4, c = f & 15;
                CP16(smaddr(&sm[VSO(nb) + r * SVD + c * 4]),
                     g_vt + (size_t)r * 8192 + j0 + c * 4);
            }
            if (tid < 16) CP16(smaddr(&sm[CKO(nb) + tid * 4]), g_ck + j0 + tid * 4);
            CP_COMMIT();
            CP_WAIT1();
        } else {
            CP_WAIT0();
        }
        __syncthreads();

        // ---- GEMM1: S = Q @ K^T (m16 x n16 x k128; all fragments via v2) ----
        float sa[2][4];
        #pragma unroll
        for (int i = 0; i < 2; i++)
            #pragma unroll
            for (int j = 0; j < 4; j++) sa[i][j] = 0.0f;

        const uint32_t* QsU = (const uint32_t*)&sm[QSO];
        const uint32_t* KsU = (const uint32_t*)&sm[KSO(b)];
        #pragma unroll
        for (int k0 = 0; k0 < 16; k0++) {
            uint2 aA = *(const uint2*)&QsU[(m0 + gid) * SQ + k0 * 8 + 2 * tig];     // a0,a2
            uint2 aB = *(const uint2*)&QsU[(m0 + gid + 8) * SQ + k0 * 8 + 2 * tig]; // a1,a3
            #pragma unroll
            for (int n0 = 0; n0 < 2; n0++) {
                uint2 bb = *(const uint2*)&KsU[(kb0 + n0 * 8 + gid) * SQ + k0 * 8 + 2 * tig];
                mma8(sa[n0], aA.x, aB.x, aA.y, aB.y, bb.x, bb.y);
            }
        }

        // ---- P = 2^(C2*S + cq + ck), den += P; store P at permuted key cols ----
        const float* ckb = &sm[CKO(b)];
        const int s2 = (tig & 1) * 4 + (tig >> 1);          // sperm(2*tig)
        #pragma unroll
        for (int n0 = 0; n0 < 2; n0++) {
            int cbl = kb0 + n0 * 8;
            float ck0 = ckb[cbl + 2 * tig], ck1 = ckb[cbl + 2 * tig + 1];
            float p00 = tf32r(ex2f(fmaf(C2, sa[n0][0], cq0 + ck0)));
            float p01 = tf32r(ex2f(fmaf(C2, sa[n0][1], cq0 + ck1)));
            float p10 = tf32r(ex2f(fmaf(C2, sa[n0][2], cq1 + ck0)));
            float p11 = tf32r(ex2f(fmaf(C2, sa[n0][3], cq1 + ck1)));
            den0 += p00 + p01;
            den1 += p10 + p11;
            int c0 = cbl + s2;
            sm[PSO + (m0 + gid) * SP + c0]         = p00;
            sm[PSO + (m0 + gid) * SP + c0 + 2]     = p01;
            sm[PSO + (m0 + gid + 8) * SP + c0]     = p10;
            sm[PSO + (m0 + gid + 8) * SP + c0 + 2] = p11;
        }
        __syncwarp();

        // ---- GEMM2: O += P @ V over this group's 16 keys (v2 fragments) ----
        const uint32_t* PsU = (const uint32_t*)&sm[PSO];
        const uint32_t* VsU = (const uint32_t*)&sm[VSO(b)];
        #pragma unroll
        for (int k0 = 0; k0 < 2; k0++) {
            uint2 aA = *(const uint2*)&PsU[(m0 + gid) * SP + kb0 + k0 * 8 + 2 * tig];
            uint2 aB = *(const uint2*)&PsU[(m0 + gid + 8) * SP + kb0 + k0 * 8 + 2 * tig];
            #pragma unroll
            for (int n0 = 0; n0 < 16; n0++) {
                uint2 bb = *(const uint2*)&VsU[(n0 * 8 + gid) * SVD + kb0 + k0 * 8 + 2 * tig];
                mma8(oa[n0], aA.x, aB.x, aA.y, aB.y, bb.x, bb.y);
            }
        }
        __syncthreads();
    }

    // ---- cross-group reduction ----
    den0 += __shfl_xor_sync(0xFFFFFFFFu, den0, 1);
    den0 += __shfl_xor_sync(0xFFFFFFFFu, den0, 2);
    den1 += __shfl_xor_sync(0xFFFFFFFFu, den1, 1);
    den1 += __shfl_xor_sync(0xFFFFFFFFu, den1, 2);

    const int rl0 = m0 + gid, rl1 = rl0 + 8;
    if (g) {
        float* ob = &sm[(g == 1) ? KSO(0) : (g == 2) ? KSO(1) : VSO(0)];
        #pragma unroll
        for (int n0 = 0; n0 < 16; n0++) {
            int col = n0 * 8 + 2 * tig;
            *(float2*)&ob[rl0 * 132 + col] = make_float2(oa[n0][0], oa[n0][1]);
            *(float2*)&ob[rl1 * 132 + col] = make_float2(oa[n0][2], oa[n0][3]);
        }
        if (tig == 0) {
            sm[PSO + (g - 1) * 64 + rl0] = den0;
            sm[PSO + (g - 1) * 64 + rl1] = den1;
        }
    }
    __syncthreads();
    if (g == 0) {
        const float* b1 = &sm[KSO(0)];
        const float* b2 = &sm[KSO(1)];
        const float* b3 = &sm[VSO(0)];
        den0 += sm[PSO + rl0] + sm[PSO + 64 + rl0] + sm[PSO + 128 + rl0];
        den1 += sm[PSO + rl1] + sm[PSO + 64 + rl1] + sm[PSO + 128 + rl1];
        const float i0 = 1.0f / den0, i1 = 1.0f / den1;
        const int row0 = r0 + rl0, row1 = r0 + rl1;
        #pragma unroll
        for (int n0 = 0; n0 < 16; n0++) {
            int col = n0 * 8 + 2 * tig;
            float2 u1 = *(const float2*)&b1[rl0 * 132 + col];
            float2 u2 = *(const float2*)&b2[rl0 * 132 + col];
            float2 u3 = *(const float2*)&b3[rl0 * 132 + col];
            if (row0 < NROWS)
                *(float2*)&out[(size_t)row0 * 128 + col] =
                    make_float2((oa[n0][0] + u1.x + u2.x + u3.x) * i0,
                                (oa[n0][1] + u1.y + u2.y + u3.y) * i0);
            float2 v1 = *(const float2*)&b1[rl1 * 132 + col];
            float2 v2 = *(const float2*)&b2[rl1 * 132 + col];
            float2 v3 = *(const float2*)&b3[rl1 * 132 + col];
            if (row1 < NROWS)
                *(float2*)&out[(size_t)row1 * 128 + col] =
                    make_float2((oa[n0][2] + v1.x + v2.x + v3.x) * i1,
                                (oa[n0][3] + v1.y + v2.y + v3.y) * i1);
        }
    }
}

// ---------------- launch ----------------------------------------------------
extern "C" void kernel_launch(void* const* d_in, const int* in_sizes, int n_in,
                              void* d_out, int out_size)
{
    const float* X = (const float*)d_in[0];   // (8192,128)
    const float* y = (const float*)d_in[1];   // (8191,128)
    const float* R = (const float*)d_in[3];   // (128,128)
    const float* t = (const float*)d_in[4];   // (128,1)
    float* out = (float*)d_out;               // (8191,128)

    cudaFuncSetAttribute(yt_kernel,   cudaFuncAttributeMaxDynamicSharedMemorySize, 102400);
    cudaFuncSetAttribute(attn_kernel, cudaFuncAttributeMaxDynamicSharedMemorySize, SMEM_BYTES);

    yt_kernel<<<128, 256, 102400>>>(y, R, t);
    norm_kernel<<<dim3(8192, 2), 128>>>(X);
    vt_kernel<<<128, 256>>>(X);
    attn_kernel<<<128, 512, SMEM_BYTES>>>(X, out);
}

// round 10
// speedup vs baseline: 1.2702x; 1.2702x over previous
#include <cuda_runtime.h>
#include <cstdint>

#define NROWS 8191
#define C2    0.011271055006945017f    /* 2*gamma*log2(e), gamma=1/256 */
#define NGL2  0.0056355275034725085f   /* gamma*log2(e) */

// ---------------- device scratch (no allocation allowed) ----------------
__device__ float g_yt[8192 * 128];   // tf32 yt keys, dims permuted within 8
__device__ float g_vt[128 * 8192];   // tf32 V transposed [dim][key], keys permuted within 8
__device__ float g_cq[8192];         // -gamma*log2e*||x_i||^2
__device__ float g_ck[8192];         // -gamma*log2e*||yt_j||^2 ; row 8191 -> -1e30

// stored index of logical k within its 8-block: (k,k+4) become adjacent
__device__ __host__ __forceinline__ int sperm(int k) { return ((k & 3) << 1) | (k >> 2); }

// ---------------- helpers ----------------
__device__ __forceinline__ float tf32r(float x) {
    uint32_t u; asm("cvt.rna.tf32.f32 %0, %1;" : "=r"(u) : "f"(x));
    return __uint_as_float(u);
}
__device__ __forceinline__ float ex2f(float x) {
    float r; asm("ex2.approx.f32 %0, %1;" : "=f"(r) : "f"(x)); return r;
}
__device__ __forceinline__ uint32_t smaddr(const void* p) {
    uint32_t a;
    asm("{ .reg .u64 t; cvta.to.shared.u64 t, %1; cvt.u32.u64 %0, t; }" : "=r"(a) : "l"(p));
    return a;
}
#define CP16(dst, src) \
    asm volatile("cp.async.cg.shared.global [%0], [%1], 16;" \
                 :: "r"(dst), "l"((size_t)__cvta_generic_to_global(src)) : "memory")
#define CP_COMMIT() asm volatile("cp.async.commit_group;" ::: "memory")
#define CP_WAIT1()  asm volatile("cp.async.wait_group 1;" ::: "memory")
#define CP_WAIT0()  asm volatile("cp.async.wait_group 0;" ::: "memory")

__device__ __forceinline__ void mma8(float* c, uint32_t a0, uint32_t a1, uint32_t a2,
                                     uint32_t a3, uint32_t b0, uint32_t b1) {
    asm volatile("mma.sync.aligned.m16n8k8.row.col.f32.tf32.tf32.f32 "
                 "{%0,%1,%2,%3}, {%4,%5,%6,%7}, {%8,%9}, {%0,%1,%2,%3};"
                 : "+f"(c[0]), "+f"(c[1]), "+f"(c[2]), "+f"(c[3])
                 : "r"(a0), "r"(a1), "r"(a2), "r"(a3), "r"(b0), "r"(b1));
}

// ---------------- kernel 1: yt = y @ R^T + t (tf32, dims permuted) ---------
__global__ __launch_bounds__(256) void yt_kernel(const float* __restrict__ y,
                                                 const float* __restrict__ R,
                                                 const float* __restrict__ t)
{
    extern __shared__ char smem[];
    float* yT = (float*)smem;                 // [k][row] stride 68
    float* RT = (float*)(smem + 34816);       // [k][c]   stride 132
    const int tid = threadIdx.x;
    const int r0  = blockIdx.x * 64;

    #pragma unroll
    for (int s = 0; s < 32; s++) {
        int e = tid + s * 256, row = e >> 7, k = e & 127, gr = r0 + row;
        yT[k * 68 + row] = (gr < NROWS) ? y[gr * 128 + k] : 0.0f;
    }
    #pragma unroll
    for (int s = 0; s < 64; s++) {
        int e = tid + s * 256, c = e >> 7, k = e & 127;
        RT[k * 132 + c] = R[e];
    }
    __syncthreads();

    const int tr = tid >> 4, tc = tid & 15;
    float acc[4][8];
    #pragma unroll
    for (int i = 0; i < 4; i++)
        #pragma unroll
        for (int j = 0; j < 8; j++) acc[i][j] = 0.0f;

    const float4* yT4 = (const float4*)yT;
    const float4* RT4 = (const float4*)RT;
    #pragma unroll 8
    for (int k = 0; k < 128; k++) {
        float4 a  = yT4[k * 17 + tr];
        float4 b0 = RT4[k * 33 + tc * 2];
        float4 b1 = RT4[k * 33 + tc * 2 + 1];
        float av[4] = {a.x, a.y, a.z, a.w};
        float bv[8] = {b0.x, b0.y, b0.z, b0.w, b1.x, b1.y, b1.z, b1.w};
        #pragma unroll
        for (int i = 0; i < 4; i++)
            #pragma unroll
            for (int j = 0; j < 8; j++) acc[i][j] += av[i] * bv[j];
    }
    float tv[8];
    #pragma unroll
    for (int j = 0; j < 8; j++) tv[j] = t[tc * 8 + j];
    #pragma unroll
    for (int i = 0; i < 4; i++) {
        int row = r0 + tr * 4 + i;
        #pragma unroll
        for (int j = 0; j < 8; j++)
            g_yt[row * 128 + tc * 8 + sperm(j)] = tf32r(acc[i][j] + tv[j]);
    }
}

// ---------------- kernel 2: scaled norms ----------------
__global__ __launch_bounds__(128) void norm_kernel(const float* __restrict__ X)
{
    const int row = blockIdx.x, which = blockIdx.y;
    float v = which ? g_yt[row * 128 + threadIdx.x]      // permuted order: sum invariant
                    : tf32r(X[row * 128 + threadIdx.x]);
    float s = v * v;
    #pragma unroll
    for (int o = 16; o; o >>= 1) s += __shfl_down_sync(0xFFFFFFFFu, s, o);
    __shared__ float red[4];
    if ((threadIdx.x & 31) == 0) red[threadIdx.x >> 5] = s;
    __syncthreads();
    if (threadIdx.x == 0) {
        float tot = -(red[0] + red[1] + red[2] + red[3]) * NGL2;
        if (which) g_ck[row] = (row < NROWS) ? tot : -1e30f;
        else       g_cq[row] = tot;
    }
}

// ---------------- kernel 3: V transpose [dim][key], keys permuted ----------
__global__ __launch_bounds__(256) void vt_kernel(const float* __restrict__ X)
{
    __shared__ float ts[64 * 133];
    const int tid = threadIdx.x;
    const int j0 = blockIdx.x * 64;

    #pragma unroll
    for (int i = 0; i < 8; i++) {
        int f = tid + i * 256;               // 0..2047
        int r = f >> 5, c4 = f & 31;
        int src = j0 + r + 1; if (src > 8191) src = 8191;  // clamp; weight is 0
        float4 v = ((const float4*)X)[(size_t)src * 32 + c4];
        float* d = &ts[r * 133 + c4 * 4];
        d[0] = v.x; d[1] = v.y; d[2] = v.z; d[3] = v.w;
    }
    __syncthreads();

    const int w = tid >> 5, l = tid & 31;
    #pragma unroll
    for (int db = 0; db < 16; db++) {
        int d = db * 8 + w;
        #pragma unroll
        for (int it = 0; it < 2; it++) {
            int r = it * 32 + l;
            int jst = (r & ~7) | sperm(r & 7);
            g_vt[(size_t)d * 8192 + j0 + jst] = tf32r(ts[r * 133 + d]);
        }
    }
}

// ---------------- kernel 4: flash RBF attention, m32 tiles + v2 loads -------
// grid 128, 128 threads (4 warps): wm=w>>1 (m32 strip), half=w&1
//   GEMM1: warp (wm,kg=half) -> S[m32][keys kg*32..+31]
//   GEMM2: warp (wm,h =half) -> O[m32][dims h*64..+63], k = all 64 keys
// strides: Q/K rows 136 floats, V/P rows 72 floats (8 mod 32 -> LDS.64 conflict-free)
#define SQ 136
#define SVD 72
#define QSO 0
#define KSO(b) (8704 + (b) * 8704)
#define VSO(b) (26112 + (b) * 9216)
#define PSO 44544
#define CKO(b) (49152 + (b) * 64)
#define DNO 49280
#define SMEM_BYTES (49408 * 4)

__global__ __launch_bounds__(128, 1) void attn_kernel(const float* __restrict__ X,
                                                      float* __restrict__ out)
{
    extern __shared__ float sm[];
    const int tid = threadIdx.x;
    const int w = tid >> 5, l = tid & 31;
    const int gid = l >> 2, tig = l & 3;
    const int wm = w >> 1, half = w & 1;
    const int mb = wm * 32;                  // warp's m-base (local)
    const int r0 = blockIdx.x * 64;
    const int s0 = ((tig & 1) << 2) | (tig >> 1);   // sperm(2*tig) in {0,4,1,5}

    // ---- stage Q (tf32, dims permuted) ----
    {
        const float4* X4 = (const float4*)X;
        #pragma unroll
        for (int i = 0; i < 16; i++) {
            int f = tid + i * 128, r = f >> 5, c4 = f & 31;
            float4 q = X4[(size_t)(r0 + r) * 32 + c4];
            int base = QSO + r * SQ + (c4 >> 1) * 8 + (c4 & 1);
            sm[base + 0] = tf32r(q.x); sm[base + 2] = tf32r(q.y);
            sm[base + 4] = tf32r(q.z); sm[base + 6] = tf32r(q.w);
        }
    }
    float cqv[4];
    #pragma unroll
    for (int j = 0; j < 4; j++) cqv[j] = g_cq[r0 + mb + gid + 8 * j];

    // ---- prime tile 0 -> buf 0 ----
    #pragma unroll
    for (int i = 0; i < 16; i++) {
        int f = tid + i * 128, r = f >> 5, c4 = f & 31;
        CP16(smaddr(&sm[KSO(0) + r * SQ + c4 * 4]), g_yt + r * 128 + c4 * 4);
    }
    #pragma unroll
    for (int i = 0; i < 16; i++) {
        int f = tid + i * 128, d = f >> 4, c = f & 15;
        CP16(smaddr(&sm[VSO(0) + d * SVD + c * 4]), g_vt + (size_t)d * 8192 + c * 4);
    }
    if (tid < 16) CP16(smaddr(&sm[CKO(0) + tid * 4]), g_ck + tid * 4);
    CP_COMMIT();
    __syncthreads();                         // Q visible to all warps

    float oa[2][8][4];
    #pragma unroll
    for (int m = 0; m < 2; m++)
        #pragma unroll
        for (int n = 0; n < 8; n++)
            #pragma unroll
            for (int j = 0; j < 4; j++) oa[m][n][j] = 0.0f;
    float dnv[4] = {0.f, 0.f, 0.f, 0.f};

    #pragma unroll 1
    for (int t = 0; t < 128; t++) {
        const int b = t & 1;

        if (t + 1 < 128) {                   // prefetch t+1 into buf b^1
            const int nb = b ^ 1;
            const int j0 = (t + 1) * 64;
            #pragma unroll
            for (int i = 0; i < 16; i++) {
                int f = tid + i * 128, r = f >> 5, c4 = f & 31;
                CP16(smaddr(&sm[KSO(nb) + r * SQ + c4 * 4]),
                     g_yt + (size_t)(j0 + r) * 128 + c4 * 4);
            }
            #pragma unroll
            for (int i = 0; i < 16; i++) {
                int f = tid + i * 128, d = f >> 4, c = f & 15;
                CP16(smaddr(&sm[VSO(nb) + d * SVD + c * 4]),
                     g_vt + (size_t)d * 8192 + j0 + c * 4);
            }
            if (tid < 16) CP16(smaddr(&sm[CKO(nb) + tid * 4]), g_ck + j0 + tid * 4);
            CP_COMMIT();
            CP_WAIT1();
        } else {
            CP_WAIT0();
        }
        __syncthreads();                     // tile t visible; prev iter fully done

        // ---- GEMM1: S = Q @ K^T  (m32 x n32 x k128; warp keys half*32..) ----
        float sa[2][4][4];
        #pragma unroll
        for (int m = 0; m < 2; m++)
            #pragma unroll
            for (int n = 0; n < 4; n++)
                #pragma unroll
                for (int j = 0; j < 4; j++) sa[m][n][j] = 0.0f;

        const uint32_t* QsU = (const uint32_t*)&sm[QSO];
        const uint32_t* KsU = (const uint32_t*)&sm[KSO(b)];
        #pragma unroll
        for (int k0 = 0; k0 < 16; k0++) {
            uint2 a00 = *(const uint2*)&QsU[(mb + gid)      * SQ + k0 * 8 + 2 * tig];
            uint2 a01 = *(const uint2*)&QsU[(mb + gid + 8)  * SQ + k0 * 8 + 2 * tig];
            uint2 a10 = *(const uint2*)&QsU[(mb + gid + 16) * SQ + k0 * 8 + 2 * tig];
            uint2 a11 = *(const uint2*)&QsU[(mb + gid + 24) * SQ + k0 * 8 + 2 * tig];
            #pragma unroll
            for (int n0 = 0; n0 < 4; n0++) {
                uint2 bb = *(const uint2*)&KsU[(half * 32 + n0 * 8 + gid) * SQ + k0 * 8 + 2 * tig];
                mma8(sa[0][n0], a00.x, a01.x, a00.y, a01.y, bb.x, bb.y);
                mma8(sa[1][n0], a10.x, a11.x, a10.y, a11.y, bb.x, bb.y);
            }
        }

        // ---- P = 2^(C2*S + cq + ck); den accum; store P (permuted slots) ----
        const float* ckb = &sm[CKO(b)];
        #pragma unroll
        for (int m = 0; m < 2; m++) {
            #pragma unroll
            for (int n0 = 0; n0 < 4; n0++) {
                int cl = half * 32 + n0 * 8;
                float ck0 = ckb[cl + 2 * tig], ck1 = ckb[cl + 2 * tig + 1];
                float p0 = tf32r(ex2f(fmaf(C2, sa[m][n0][0], cqv[2 * m]     + ck0)));
                float p1 = tf32r(ex2f(fmaf(C2, sa[m][n0][1], cqv[2 * m]     + ck1)));
                float p2 = tf32r(ex2f(fmaf(C2, sa[m][n0][2], cqv[2 * m + 1] + ck0)));
                float p3 = tf32r(ex2f(fmaf(C2, sa[m][n0][3], cqv[2 * m + 1] + ck1)));
                dnv[2 * m]     += p0 + p1;
                dnv[2 * m + 1] += p2 + p3;
                int rA = mb + gid + 16 * m, rB = rA + 8;
                sm[PSO + rA * SVD + cl + s0]     = p0;
                sm[PSO + rA * SVD + cl + s0 + 2] = p1;
                sm[PSO + rB * SVD + cl + s0]     = p2;
                sm[PSO + rB * SVD + cl + s0 + 2] = p3;
            }
        }
        asm volatile("bar.sync %0, %1;" :: "r"(1 + wm), "r"(64) : "memory");

        // ---- GEMM2: O += P @ V  (m32 x n64 x k64; warp dims half*64..) ----
        const uint32_t* PsU = (const uint32_t*)&sm[PSO];
        const uint32_t* VsU = (const uint32_t*)&sm[VSO(b)];
        #pragma unroll
        for (int k0 = 0; k0 < 8; k0++) {
            uint2 p0 = *(const uint2*)&PsU[(mb + gid)      * SVD + k0 * 8 + 2 * tig];
            uint2 p1 = *(const uint2*)&PsU[(mb + gid + 8)  * SVD + k0 * 8 + 2 * tig];
            uint2 p2 = *(const uint2*)&PsU[(mb + gid + 16) * SVD + k0 * 8 + 2 * tig];
            uint2 p3 = *(const uint2*)&PsU[(mb + gid + 24) * SVD + k0 * 8 + 2 * tig];
            #pragma unroll
            for (int n0 = 0; n0 < 8; n0++) {
                uint2 vb = *(const uint2*)&VsU[(half * 64 + n0 * 8 + gid) * SVD + k0 * 8 + 2 * tig];
                mma8(oa[0][n0], p0.x, p1.x, p0.y, p1.y, vb.x, vb.y);
                mma8(oa[1][n0], p2.x, p3.x, p2.y, p3.y, vb.x, vb.y);
            }
        }
        __syncthreads();                     // release buf b + P block
    }

    // ---- den: reduce over tig, combine key-halves via smem ----
    #pragma unroll
    for (int j = 0; j < 4; j++) {
        dnv[j] += __shfl_xor_sync(0xFFFFFFFFu, dnv[j], 1);
        dnv[j] += __shfl_xor_sync(0xFFFFFFFFu, dnv[j], 2);
    }
    if (tig == 0) {
        #pragma unroll
        for (int j = 0; j < 4; j++)
            sm[DNO + half * 64 + mb + gid + 8 * j] = dnv[j];
    }
    __syncthreads();

    // ---- normalize + write (warp covers dims half*64..+63 of its m32) ----
    #pragma unroll
    for (int m = 0; m < 2; m++) {
        int rA = mb + gid + 16 * m, rB = rA + 8;
        float iA = 1.0f / (sm[DNO + rA] + sm[DNO + 64 + rA]);
        float iB = 1.0f / (sm[DNO + rB] + sm[DNO + 64 + rB]);
        int gA = r0 + rA, gB = r0 + rB;
        #pragma unroll
        for (int n0 = 0; n0 < 8; n0++) {
            int col = half * 64 + n0 * 8 + 2 * tig;
            if (gA < NROWS)
                *(float2*)&out[(size_t)gA * 128 + col] =
                    make_float2(oa[m][n0][0] * iA, oa[m][n0][1] * iA);
            if (gB < NROWS)
                *(float2*)&out[(size_t)gB * 128 + col] =
                    make_float2(oa[m][n0][2] * iB, oa[m][n0][3] * iB);
        }
    }
}

// ---------------- launch ----------------------------------------------------
extern "C" void kernel_launch(void* const* d_in, const int* in_sizes, int n_in,
                              void* d_out, int out_size)
{
    const float* X = (const float*)d_in[0];   // (8192,128)
    const float* y = (const float*)d_in[1];   // (8191,128)
    const float* R = (const float*)d_in[3];   // (128,128)
    const float* t = (const float*)d_in[4];   // (128,1)
    float* out = (float*)d_out;               // (8191,128)

    cudaFuncSetAttribute(yt_kernel,   cudaFuncAttributeMaxDynamicSharedMemorySize, 102400);
    cudaFuncSetAttribute(attn_kernel, cudaFuncAttributeMaxDynamicSharedMemorySize, SMEM_BYTES);

    yt_kernel<<<128, 256, 102400>>>(y, R, t);
    norm_kernel<<<dim3(8192, 2), 128>>>(X);
    vt_kernel<<<128, 256>>>(X);
    attn_kernel<<<128, 128, SMEM_BYTES>>>(X, out);
}

// round 11
// speedup vs baseline: 1.6203x; 1.2756x over previous
#include <cuda_runtime.h>
#include <cstdint>

#define NROWS 8191
#define C2    0.011271055006945017f    /* 2*gamma*log2(e), gamma=1/256 */
#define NGL2  0.0056355275034725085f   /* gamma*log2(e) */

// ---------------- device scratch (no allocation allowed) ----------------
__device__ float g_yt[8192 * 128];   // tf32 yt keys, dims permuted within 8
__device__ float g_vt[128 * 8192];   // tf32 V transposed [dim][key], keys permuted within 8
__device__ float g_cq[8192];         // -gamma*log2e*||x_i||^2
__device__ float g_ck[8192];         // -gamma*log2e*||yt_j||^2 ; row 8191 -> -1e30

// stored index of logical k within its 8-block: (k,k+4) become adjacent
__device__ __host__ __forceinline__ int sperm(int k) { return ((k & 3) << 1) | (k >> 2); }

// ---------------- helpers ----------------
__device__ __forceinline__ float tf32r(float x) {
    uint32_t u; asm("cvt.rna.tf32.f32 %0, %1;" : "=r"(u) : "f"(x));
    return __uint_as_float(u);
}
__device__ __forceinline__ float ex2f(float x) {
    float r; asm("ex2.approx.f32 %0, %1;" : "=f"(r) : "f"(x)); return r;
}
__device__ __forceinline__ uint32_t smaddr(const void* p) {
    uint32_t a;
    asm("{ .reg .u64 t; cvta.to.shared.u64 t, %1; cvt.u32.u64 %0, t; }" : "=r"(a) : "l"(p));
    return a;
}
#define CP16(dst, src) \
    asm volatile("cp.async.cg.shared.global [%0], [%1], 16;" \
                 :: "r"(dst), "l"((size_t)__cvta_generic_to_global(src)) : "memory")
#define CP_COMMIT() asm volatile("cp.async.commit_group;" ::: "memory")
#define CP_WAIT1()  asm volatile("cp.async.wait_group 1;" ::: "memory")
#define CP_WAIT0()  asm volatile("cp.async.wait_group 0;" ::: "memory")

__device__ __forceinline__ void mma8(float* c, uint32_t a0, uint32_t a1, uint32_t a2,
                                     uint32_t a3, uint32_t b0, uint32_t b1) {
    asm volatile("mma.sync.aligned.m16n8k8.row.col.f32.tf32.tf32.f32 "
                 "{%0,%1,%2,%3}, {%4,%5,%6,%7}, {%8,%9}, {%0,%1,%2,%3};"
                 : "+f"(c[0]), "+f"(c[1]), "+f"(c[2]), "+f"(c[3])
                 : "r"(a0), "r"(a1), "r"(a2), "r"(a3), "r"(b0), "r"(b1));
}

// ---------------- kernel 1: yt = y @ R^T + t (tf32, dims permuted) ---------
__global__ __launch_bounds__(256) void yt_kernel(const float* __restrict__ y,
                                                 const float* __restrict__ R,
                                                 const float* __restrict__ t)
{
    extern __shared__ char smem[];
    float* yT = (float*)smem;                 // [k][row] stride 68
    float* RT = (float*)(smem + 34816);       // [k][c]   stride 132
    const int tid = threadIdx.x;
    const int r0  = blockIdx.x * 64;

    #pragma unroll
    for (int s = 0; s < 32; s++) {
        int e = tid + s * 256, row = e >> 7, k = e & 127, gr = r0 + row;
        yT[k * 68 + row] = (gr < NROWS) ? y[gr * 128 + k] : 0.0f;
    }
    #pragma unroll
    for (int s = 0; s < 64; s++) {
        int e = tid + s * 256, c = e >> 7, k = e & 127;
        RT[k * 132 + c] = R[e];
    }
    __syncthreads();

    const int tr = tid >> 4, tc = tid & 15;
    float acc[4][8];
    #pragma unroll
    for (int i = 0; i < 4; i++)
        #pragma unroll
        for (int j = 0; j < 8; j++) acc[i][j] = 0.0f;

    const float4* yT4 = (const float4*)yT;
    const float4* RT4 = (const float4*)RT;
    #pragma unroll 8
    for (int k = 0; k < 128; k++) {
        float4 a  = yT4[k * 17 + tr];
        float4 b0 = RT4[k * 33 + tc * 2];
        float4 b1 = RT4[k * 33 + tc * 2 + 1];
        float av[4] = {a.x, a.y, a.z, a.w};
        float bv[8] = {b0.x, b0.y, b0.z, b0.w, b1.x, b1.y, b1.z, b1.w};
        #pragma unroll
        for (int i = 0; i < 4; i++)
            #pragma unroll
            for (int j = 0; j < 8; j++) acc[i][j] += av[i] * bv[j];
    }
    float tv[8];
    #pragma unroll
    for (int j = 0; j < 8; j++) tv[j] = t[tc * 8 + j];
    #pragma unroll
    for (int i = 0; i < 4; i++) {
        int row = r0 + tr * 4 + i;
        #pragma unroll
        for (int j = 0; j < 8; j++)
            g_yt[row * 128 + tc * 8 + sperm(j)] = tf32r(acc[i][j] + tv[j]);
    }
}

// ---------------- kernel 2: scaled norms ----------------
__global__ __launch_bounds__(128) void norm_kernel(const float* __restrict__ X)
{
    const int row = blockIdx.x, which = blockIdx.y;
    float v = which ? g_yt[row * 128 + threadIdx.x]      // permuted order: sum invariant
                    : tf32r(X[row * 128 + threadIdx.x]);
    float s = v * v;
    #pragma unroll
    for (int o = 16; o; o >>= 1) s += __shfl_down_sync(0xFFFFFFFFu, s, o);
    __shared__ float red[4];
    if ((threadIdx.x & 31) == 0) red[threadIdx.x >> 5] = s;
    __syncthreads();
    if (threadIdx.x == 0) {
        float tot = -(red[0] + red[1] + red[2] + red[3]) * NGL2;
        if (which) g_ck[row] = (row < NROWS) ? tot : -1e30f;
        else       g_cq[row] = tot;
    }
}

// ---------------- kernel 3: V transpose [dim][key], keys permuted ----------
__global__ __launch_bounds__(256) void vt_kernel(const float* __restrict__ X)
{
    __shared__ float ts[64 * 133];
    const int tid = threadIdx.x;
    const int j0 = blockIdx.x * 64;

    #pragma unroll
    for (int i = 0; i < 8; i++) {
        int f = tid + i * 256;               // 0..2047
        int r = f >> 5, c4 = f & 31;
        int src = j0 + r + 1; if (src > 8191) src = 8191;  // clamp; weight is 0
        float4 v = ((const float4*)X)[(size_t)src * 32 + c4];
        float* d = &ts[r * 133 + c4 * 4];
        d[0] = v.x; d[1] = v.y; d[2] = v.z; d[3] = v.w;
    }
    __syncthreads();

    const int w = tid >> 5, l = tid & 31;
    #pragma unroll
    for (int db = 0; db < 16; db++) {
        int d = db * 8 + w;
        #pragma unroll
        for (int it = 0; it < 2; it++) {
            int r = it * 32 + l;
            int jst = (r & ~7) | sperm(r & 7);
            g_vt[(size_t)d * 8192 + j0 + jst] = tf32r(ts[r * 133 + d]);
        }
    }
}

// ---------------- kernel 4: flash RBF attention, 8 warps, kv-split ---------
// grid 128, 256 threads (8 warps): wm=w>>2 (m32 strip), half=(w>>1)&1, kv=w&1
//   GEMM1: warp -> S[m32][16 keys], quarter q = 2*kv + half
//   GEMM2: warp -> partial O[m32][dims half*64..+63] over keys [kv*32,+32)
//   end:   kv=1 parks O/den in retired smem; kv=0 reduces and writes.
// strides: Q/K rows 136 floats, V/P rows 72 (=8 mod 32 -> conflict-free LDS.64)
#define SQ 136
#define SVD 72
#define QSO 0
#define KSO(b) (8704 + (b) * 8704)
#define VSO(b) (26112 + (b) * 9216)
#define PSO 44544
#define CKO(b) (49152 + (b) * 64)
#define DNO 49280
#define SMEM_BYTES (49536 * 4)

__global__ __launch_bounds__(256, 1) void attn_kernel(const float* __restrict__ X,
                                                      float* __restrict__ out)
{
    extern __shared__ float sm[];
    const int tid = threadIdx.x;
    const int w = tid >> 5, l = tid & 31;
    const int gid = l >> 2, tig = l & 3;
    const int wm = w >> 2, half = (w >> 1) & 1, kv = w & 1;
    const int q = 2 * kv + half;             // GEMM1 key quarter
    const int mb = wm * 32;
    const int r0 = blockIdx.x * 64;
    const int s0 = ((tig & 1) << 2) | (tig >> 1);   // sperm(2*tig)

    // ---- stage Q (tf32, dims permuted) ----
    {
        const float4* X4 = (const float4*)X;
        #pragma unroll
        for (int i = 0; i < 8; i++) {
            int f = tid + i * 256, r = f >> 5, c4 = f & 31;
            float4 qv = X4[(size_t)(r0 + r) * 32 + c4];
            int base = QSO + r * SQ + (c4 >> 1) * 8 + (c4 & 1);
            sm[base + 0] = tf32r(qv.x); sm[base + 2] = tf32r(qv.y);
            sm[base + 4] = tf32r(qv.z); sm[base + 6] = tf32r(qv.w);
        }
    }
    float cqv[4];
    #pragma unroll
    for (int j = 0; j < 4; j++) cqv[j] = g_cq[r0 + mb + gid + 8 * j];

    // ---- prime tile 0 -> buf 0 ----
    #pragma unroll
    for (int i = 0; i < 8; i++) {
        int f = tid + i * 256, r = f >> 5, c4 = f & 31;
        CP16(smaddr(&sm[KSO(0) + r * SQ + c4 * 4]), g_yt + r * 128 + c4 * 4);
    }
    #pragma unroll
    for (int i = 0; i < 8; i++) {
        int f = tid + i * 256, d = f >> 4, c = f & 15;
        CP16(smaddr(&sm[VSO(0) + d * SVD + c * 4]), g_vt + (size_t)d * 8192 + c * 4);
    }
    if (tid < 16) CP16(smaddr(&sm[CKO(0) + tid * 4]), g_ck + tid * 4);
    CP_COMMIT();
    __syncthreads();                         // Q visible to all warps

    float oa[2][8][4];
    #pragma unroll
    for (int m = 0; m < 2; m++)
        #pragma unroll
        for (int n = 0; n < 8; n++)
            #pragma unroll
            for (int j = 0; j < 4; j++) oa[m][n][j] = 0.0f;
    float dnv[4] = {0.f, 0.f, 0.f, 0.f};

    #pragma unroll 1
    for (int t = 0; t < 128; t++) {
        const int b = t & 1;

        if (t + 1 < 128) {                   // prefetch t+1 into buf b^1
            const int nb = b ^ 1;
            const int j0 = (t + 1) * 64;
            #pragma unroll
            for (int i = 0; i < 8; i++) {
                int f = tid + i * 256, r = f >> 5, c4 = f & 31;
                CP16(smaddr(&sm[KSO(nb) + r * SQ + c4 * 4]),
                     g_yt + (size_t)(j0 + r) * 128 + c4 * 4);
            }
            #pragma unroll
            for (int i = 0; i < 8; i++) {
                int f = tid + i * 256, d = f >> 4, c = f & 15;
                CP16(smaddr(&sm[VSO(nb) + d * SVD + c * 4]),
                     g_vt + (size_t)d * 8192 + j0 + c * 4);
            }
            if (tid < 16) CP16(smaddr(&sm[CKO(nb) + tid * 4]), g_ck + j0 + tid * 4);
            CP_COMMIT();
            CP_WAIT1();
        } else {
            CP_WAIT0();
        }
        __syncthreads();                     // tile t visible; prev tile fully done

        // ---- GEMM1: S[m32][16 keys q*16..] = Q @ K^T ----
        float sa[2][2][4];
        #pragma unroll
        for (int m = 0; m < 2; m++)
            #pragma unroll
            for (int n = 0; n < 2; n++)
                #pragma unroll
                for (int j = 0; j < 4; j++) sa[m][n][j] = 0.0f;

        const uint32_t* QsU = (const uint32_t*)&sm[QSO];
        const uint32_t* KsU = (const uint32_t*)&sm[KSO(b)];
        #pragma unroll
        for (int k0 = 0; k0 < 16; k0++) {
            uint2 a00 = *(const uint2*)&QsU[(mb + gid)      * SQ + k0 * 8 + 2 * tig];
            uint2 a01 = *(const uint2*)&QsU[(mb + gid + 8)  * SQ + k0 * 8 + 2 * tig];
            uint2 a10 = *(const uint2*)&QsU[(mb + gid + 16) * SQ + k0 * 8 + 2 * tig];
            uint2 a11 = *(const uint2*)&QsU[(mb + gid + 24) * SQ + k0 * 8 + 2 * tig];
            #pragma unroll
            for (int n0 = 0; n0 < 2; n0++) {
                uint2 bb = *(const uint2*)&KsU[(q * 16 + n0 * 8 + gid) * SQ + k0 * 8 + 2 * tig];
                mma8(sa[0][n0], a00.x, a01.x, a00.y, a01.y, bb.x, bb.y);
                mma8(sa[1][n0], a10.x, a11.x, a10.y, a11.y, bb.x, bb.y);
            }
        }

        // ---- P = 2^(C2*S + cq + ck); den accum; store P (permuted slots) ----
        const float* ckb = &sm[CKO(b)];
        #pragma unroll
        for (int m = 0; m < 2; m++) {
            #pragma unroll
            for (int n0 = 0; n0 < 2; n0++) {
                int cl = q * 16 + n0 * 8;
                float ck0 = ckb[cl + 2 * tig], ck1 = ckb[cl + 2 * tig + 1];
                float p0 = tf32r(ex2f(fmaf(C2, sa[m][n0][0], cqv[2 * m]     + ck0)));
                float p1 = tf32r(ex2f(fmaf(C2, sa[m][n0][1], cqv[2 * m]     + ck1)));
                float p2 = tf32r(ex2f(fmaf(C2, sa[m][n0][2], cqv[2 * m + 1] + ck0)));
                float p3 = tf32r(ex2f(fmaf(C2, sa[m][n0][3], cqv[2 * m + 1] + ck1)));
                dnv[2 * m]     += p0 + p1;
                dnv[2 * m + 1] += p2 + p3;
                int rA = mb + gid + 16 * m, rB = rA + 8;
                sm[PSO + rA * SVD + cl + s0]     = p0;
                sm[PSO + rA * SVD + cl + s0 + 2] = p1;
                sm[PSO + rB * SVD + cl + s0]     = p2;
                sm[PSO + rB * SVD + cl + s0 + 2] = p3;
            }
        }
        // sync the 2 warps sharing (wm,kv): producers of quarters 2kv,2kv+1
        asm volatile("bar.sync %0, %1;" :: "r"(1 + wm * 2 + kv), "r"(64) : "memory");

        // ---- GEMM2: O[m32][dims half*64..] += P @ V over keys [kv*32,+32) ----
        const uint32_t* PsU = (const uint32_t*)&sm[PSO];
        const uint32_t* VsU = (const uint32_t*)&sm[VSO(b)];
        #pragma unroll
        for (int k0 = 0; k0 < 4; k0++) {
            int kc = kv * 32 + k0 * 8 + 2 * tig;
            uint2 p0 = *(const uint2*)&PsU[(mb + gid)      * SVD + kc];
            uint2 p1 = *(const uint2*)&PsU[(mb + gid + 8)  * SVD + kc];
            uint2 p2 = *(const uint2*)&PsU[(mb + gid + 16) * SVD + kc];
            uint2 p3 = *(const uint2*)&PsU[(mb + gid + 24) * SVD + kc];
            #pragma unroll
            for (int n0 = 0; n0 < 8; n0++) {
                uint2 vb = *(const uint2*)&VsU[(half * 64 + n0 * 8 + gid) * SVD + kc];
                mma8(oa[0][n0], p0.x, p1.x, p0.y, p1.y, vb.x, vb.y);
                mma8(oa[1][n0], p2.x, p3.x, p2.y, p3.y, vb.x, vb.y);
            }
        }
        __syncthreads();                     // release buf b + P block
    }

    // ---- epilogue: den quarters -> smem; kv=1 parks partial O ----
    #pragma unroll
    for (int j = 0; j < 4; j++) {
        dnv[j] += __shfl_xor_sync(0xFFFFFFFFu, dnv[j], 1);
        dnv[j] += __shfl_xor_sync(0xFFFFFFFFu, dnv[j], 2);
    }
    if (tig == 0) {
        #pragma unroll
        for (int j = 0; j < 4; j++)
            sm[DNO + q * 64 + mb + gid + 8 * j] = dnv[j];
    }
    if (kv) {                                // park partial O in retired K buf 0
        float* ob = &sm[KSO(0)];
        #pragma unroll
        for (int m = 0; m < 2; m++) {
            int rA = mb + gid + 16 * m, rB = rA + 8;
            #pragma unroll
            for (int n0 = 0; n0 < 8; n0++) {
                int col = half * 64 + n0 * 8 + 2 * tig;
                *(float2*)&ob[rA * 132 + col] = make_float2(oa[m][n0][0], oa[m][n0][1]);
                *(float2*)&ob[rB * 132 + col] = make_float2(oa[m][n0][2], oa[m][n0][3]);
            }
        }
    }
    __syncthreads();

    if (!kv) {                               // reduce + normalize + write
        const float* ob = &sm[KSO(0)];
        #pragma unroll
        for (int m = 0; m < 2; m++) {
            int rA = mb + gid + 16 * m, rB = rA + 8;
            float dA = sm[DNO + rA] + sm[DNO + 64 + rA] + sm[DNO + 128 + rA] + sm[DNO + 192 + rA];
            float dB = sm[DNO + rB] + sm[DNO + 64 + rB] + sm[DNO + 128 + rB] + sm[DNO + 192 + rB];
            float iA = 1.0f / dA, iB = 1.0f / dB;
            int gA = r0 + rA, gB = r0 + rB;
            #pragma unroll
            for (int n0 = 0; n0 < 8; n0++) {
                int col = half * 64 + n0 * 8 + 2 * tig;
                float2 uA = *(const float2*)&ob[rA * 132 + col];
                float2 uB = *(const float2*)&ob[rB * 132 + col];
                if (gA < NROWS)
                    *(float2*)&out[(size_t)gA * 128 + col] =
                        make_float2((oa[m][n0][0] + uA.x) * iA, (oa[m][n0][1] + uA.y) * iA);
                if (gB < NROWS)
                    *(float2*)&out[(size_t)gB * 128 + col] =
                        make_float2((oa[m][n0][2] + uB.x) * iB, (oa[m][n0][3] + uB.y) * iB);
            }
        }
    }
}

// ---------------- launch ----------------------------------------------------
extern "C" void kernel_launch(void* const* d_in, const int* in_sizes, int n_in,
                              void* d_out, int out_size)
{
    const float* X = (const float*)d_in[0];   // (8192,128)
    const float* y = (const float*)d_in[1];   // (8191,128)
    const float* R = (const float*)d_in[3];   // (128,128)
    const float* t = (const float*)d_in[4];   // (128,1)
    float* out = (float*)d_out;               // (8191,128)

    cudaFuncSetAttribute(yt_kernel,   cudaFuncAttributeMaxDynamicSharedMemorySize, 102400);
    cudaFuncSetAttribute(attn_kernel, cudaFuncAttributeMaxDynamicSharedMemorySize, SMEM_BYTES);

    yt_kernel<<<128, 256, 102400>>>(y, R, t);
    norm_kernel<<<dim3(8192, 2), 128>>>(X);
    vt_kernel<<<128, 256>>>(X);
    attn_kernel<<<128, 256, SMEM_BYTES>>>(X, out);
}